// round 13
// baseline (speedup 1.0000x reference)
#include <cuda_runtime.h>
#include <cstdint>

#define DIMN 384
#define NP 192                    // logical uint2 slots per B row (full K)
#define PSB 52                    // B pitch in uint2 (48 data + 4 pad), in gmem AND smem
#define A4_CNT 3072               // uint4 per 32-row A block (full K)
#define A4_PER_CHUNK 768          // uint4 per K=96 chunk
#define ABYTES_C (A4_PER_CHUNK * 16)      // 12288
#define BPAD_CHUNK (32 * PSB)     // uint2 per (ntile, chunk) block
#define BBYTES_C (BPAD_CHUNK * 8) // 13312
#define STAGE_B (ABYTES_C + BBYTES_C)     // 25600
#define SMEM_GEMM (2 * STAGE_B)   // 51200 -> 4 CTAs/SM

// Scratch (no cudaMalloc allowed)
// A: interleaved uint4 [rb][ks][p][t4]; chunk-contiguous (12288B per chunk)
__device__ __align__(16) uint4 g_v1p4[32 * A4_CNT];
__device__ __align__(16) uint4 g_tp4[32 * A4_CNT];
// B: padded chunk-major [ntile(12)][chunk(4)][row(32)][PSB uint2]
__device__ __align__(16) uint2 g_lwp[12 * 4 * BPAD_CHUNK];
__device__ __align__(16) uint2 g_Ptp[12 * 4 * BPAD_CHUNK];
__device__ float g_cbar[DIMN];

__device__ __forceinline__ uint32_t f2tf32(float x) {
    uint32_t y; asm("cvt.rna.tf32.f32 %0, %1;" : "=r"(y) : "f"(x)); return y;
}
__device__ __forceinline__ uint32_t smem_u32(const void* p) {
    uint32_t a;
    asm("{ .reg .u64 t; cvta.to.shared.u64 t, %1; cvt.u32.u64 %0, t; }" : "=r"(a) : "l"(p));
    return a;
}
__device__ __forceinline__ void mbar_init(uint32_t mb, uint32_t cnt) {
    asm volatile("mbarrier.init.shared.b64 [%0], %1;" :: "r"(mb), "r"(cnt) : "memory");
}
__device__ __forceinline__ void mbar_inval(uint32_t mb) {
    asm volatile("mbarrier.inval.shared.b64 [%0];" :: "r"(mb) : "memory");
}
__device__ __forceinline__ void mbar_expect(uint32_t mb, uint32_t tx) {
    asm volatile("mbarrier.arrive.expect_tx.shared.b64 _, [%0], %1;" :: "r"(mb), "r"(tx) : "memory");
}
#define MBAR_WAIT(mb, ph) do { \
    asm volatile("{\n\t.reg .pred P1;\n\t" \
        "WAIT_LOOP_%=:\n\t" \
        "mbarrier.try_wait.parity.acquire.cta.shared::cta.b64 P1, [%0], %1, 0x989680;\n\t" \
        "@P1 bra.uni WAIT_DONE_%=;\n\t" \
        "bra.uni WAIT_LOOP_%=;\n\t" \
        "WAIT_DONE_%=:\n\t}" :: "r"(mb), "r"((uint32_t)(ph)) : "memory"); \
} while (0)
__device__ __forceinline__ void bulk_g2s(uint32_t dst, const void* src,
                                         uint32_t bytes, uint32_t mb) {
    asm volatile(
        "cp.async.bulk.shared::cluster.global.mbarrier::complete_tx::bytes [%0], [%1], %2, [%3];"
        :: "r"(dst), "l"(src), "r"(bytes), "r"(mb) : "memory");
}
__device__ __forceinline__ void mma8(float* d, const uint32_t* a, uint32_t b0, uint32_t b1) {
    asm("mma.sync.aligned.m16n8k8.row.col.f32.tf32.tf32.f32 "
        "{%0,%1,%2,%3}, {%4,%5,%6,%7}, {%8,%9}, {%0,%1,%2,%3};"
        : "+f"(d[0]), "+f"(d[1]), "+f"(d[2]), "+f"(d[3])
        : "r"(a[0]), "r"(a[1]), "r"(a[2]), "r"(a[3]), "r"(b0), "r"(b1));
}

// ---------------------------------------------------------------------------
// cvt_pack: blocks [0,384): v1 -> g_v1p4.  blocks [384,672): lin_W -> g_lwp
// (padded chunk-major). Zeroes cbar.
// ---------------------------------------------------------------------------
__global__ __launch_bounds__(256)
void cvt_pack_kernel(const float* __restrict__ v1, const float* __restrict__ linW) {
    const int bid = blockIdx.x, tid = threadIdx.x;
    if (bid < 384) {
        const int idx = bid * 256 + tid;
        const int rb = idx / A4_CNT, rem = idx - rb * A4_CNT;
        const int ks = rem >> 6, p = (rem >> 2) & 15, t4 = rem & 3;
        const int r = rb * 32 + (p & 7) + ((p >> 3) << 4);
        const int k0 = ks * 8 + t4;
        const float* s0 = v1 + r * DIMN + k0;
        const float* s1 = s0 + 8 * DIMN;
        g_v1p4[idx] = make_uint4(f2tf32(s0[0]), f2tf32(s0[4]),
                                 f2tf32(s1[0]), f2tf32(s1[4]));
        if (idx < DIMN) g_cbar[idx] = 0.f;
    } else {
        const int idx = (bid - 384) * 256 + tid;   // 0..73727
        const int row = idx / NP, s = idx - row * NP;
        const int k0 = (s >> 2) * 8 + (s & 3);
        const float* src = linW + row * DIMN + k0;
        const int nblk = row >> 5, rloc = row & 31;
        const int chunk = s / 48, sloc = s - chunk * 48;
        g_lwp[((nblk * 4 + chunk) * 32 + rloc) * PSB + sloc] =
            make_uint2(f2tf32(src[0]), f2tf32(src[4]));
    }
}

// ---------------------------------------------------------------------------
// prep: per 32x32 tile: p = prod(1-W_k), c = chain bias.
// g_Ptp (padded chunk-major) gets rw[i]*p transposed; cbar[j] += rw[i]*c.
// ---------------------------------------------------------------------------
__global__ __launch_bounds__(256)
void prep_kernel(const float* __restrict__ W, const float* __restrict__ Bb,
                 const float* __restrict__ rw, int nblocks) {
    __shared__ float pt[32][33];
    __shared__ float cp[32][33];
    const int tid = threadIdx.x;
    const int bi = blockIdx.x, bj = blockIdx.y;
    const int il = tid >> 3, j4 = (tid & 7) * 4;
    const int gi = bi * 32 + il, gj = bj * 32 + j4;

    float4 p = make_float4(1.f, 1.f, 1.f, 1.f);
    float4 c = make_float4(0.f, 0.f, 0.f, 0.f);
    for (int k = 0; k < nblocks; k++) {
        float4 w = *(const float4*)&W[(size_t)k * DIMN * DIMN + gi * DIMN + gj];
        float4 b = *(const float4*)&Bb[(size_t)k * DIMN * DIMN + gi * DIMN + gj];
        float4 om = make_float4(1.f - w.x, 1.f - w.y, 1.f - w.z, 1.f - w.w);
        p.x *= om.x; p.y *= om.y; p.z *= om.z; p.w *= om.w;
        c.x = c.x * om.x + b.x; c.y = c.y * om.y + b.y;
        c.z = c.z * om.z + b.z; c.w = c.w * om.w + b.w;
    }
    const float ri = rw[gi];
    pt[il][j4] = ri * p.x; pt[il][j4 + 1] = ri * p.y;
    pt[il][j4 + 2] = ri * p.z; pt[il][j4 + 3] = ri * p.w;
    cp[il][j4] = ri * c.x; cp[il][j4 + 1] = ri * c.y;
    cp[il][j4 + 2] = ri * c.z; cp[il][j4 + 3] = ri * c.w;
    __syncthreads();

    if (tid < 32) {
        float s = 0.f;
#pragma unroll
        for (int i = 0; i < 32; i++) s += cp[i][tid];
        atomicAdd(&g_cbar[bj * 32 + tid], s);
    }
    // padded chunk-major transposed pack: slot S = bi*16+s; chunk=bi/3
#pragma unroll
    for (int q = tid; q < 512; q += 256) {
        int j = q >> 4, s = q & 15;
        int i0 = (s >> 2) * 8 + (s & 3);
        int dst = ((bj * 4 + bi / 3) * 32 + j) * PSB + (bi % 3) * 16 + s;
        g_Ptp[dst] = make_uint2(f2tf32(pt[i0][j]), f2tf32(pt[i0 + 4][j]));
    }
}

// ---------------------------------------------------------------------------
// tf32 mma.sync GEMM, 32x32 tile / CTA, 256 thr / 8 warps = wn(2) x kh(4).
// K = 4 chunks of 96; 2-stage ring filled by cp.async.bulk (2 copies/chunk,
// one issuing thread) tracked by mbarrier expect_tx. Per chunk each kh-warp:
// 3 ks-steps (2 LDS.128 + 2 LDS.64 -> 4 MMA). Cross-quarter smem reduction.
// MODE 0: t = v2 .* (v1 @ rwP) - cbar   (out: g_tp4, interleaved packed)
// MODE 1: out = (t @ linW^T) + linb     (out: f32 d_out)
// ---------------------------------------------------------------------------
template <int MODE>
__global__ __launch_bounds__(256, 4)
void mma_gemm(const uint4* __restrict__ Ap4, const uint2* __restrict__ Bp,
              const float* __restrict__ v2, const float* __restrict__ cbar,
              const float* __restrict__ linb, void* __restrict__ OutV) {
    extern __shared__ __align__(16) char smc[];
    __shared__ __align__(8) uint64_t mbar_sh[2];

    const int tid = threadIdx.x, lane = tid & 31, wid = tid >> 5;
    const int g = lane >> 2, t4 = lane & 3;
    const int wn = wid & 1, kh = wid >> 1;
    const int rb = blockIdx.y;
    const int m0 = rb * 32, n0 = blockIdx.x * 32;

    const uint32_t sbase = smem_u32(smc);
    const uint32_t mb0 = smem_u32(mbar_sh);
    const char* aSrc = (const char*)(Ap4 + (size_t)rb * A4_CNT);
    const char* bSrc = (const char*)(Bp + (size_t)blockIdx.x * 4 * BPAD_CHUNK);

    if (tid == 0) { mbar_init(mb0, 1); mbar_init(mb0 + 8, 1); }
    __syncthreads();

    // issue chunk c into ring buffer buf (single thread)
    auto issueChunk = [&](int c, int buf) {
        const uint32_t mb = mb0 + buf * 8;
        mbar_expect(mb, STAGE_B);
        bulk_g2s(sbase + buf * STAGE_B, aSrc + c * ABYTES_C, ABYTES_C, mb);
        bulk_g2s(sbase + buf * STAGE_B + ABYTES_C, bSrc + c * BBYTES_C, BBYTES_C, mb);
    };

    if (tid == 0) { issueChunk(0, 0); issueChunk(1, 1); }

    float acc[2][2][4] = {};

#pragma unroll
    for (int c = 0; c < 4; c++) {
        const int buf = c & 1;
        MBAR_WAIT(mb0 + buf * 8, c >> 1);

        const uint4* A4b = (const uint4*)(smc + buf * STAGE_B);
        const uint2* Bsb = (const uint2*)(smc + buf * STAGE_B + ABYTES_C);
        const uint4* aP = &A4b[kh * 3 * 64 + g * 4 + t4];           // +64/l, +32 mi
        const uint2* bP = &Bsb[(wn * 16 + g) * PSB + kh * 12 + t4]; // +4/l, +8*PSB nf
#pragma unroll
        for (int l = 0; l < 3; l++) {
            uint4 qa0 = aP[l * 64], qa1 = aP[l * 64 + 32];
            uint2 qb0 = bP[l * 4],  qb1 = bP[8 * PSB + l * 4];
            uint32_t a0[4] = {qa0.x, qa0.z, qa0.y, qa0.w};
            uint32_t a1[4] = {qa1.x, qa1.z, qa1.y, qa1.w};
            mma8(acc[0][0], a0, qb0.x, qb0.y);
            mma8(acc[0][1], a0, qb1.x, qb1.y);
            mma8(acc[1][0], a1, qb0.x, qb0.y);
            mma8(acc[1][1], a1, qb1.x, qb1.y);
        }
        __syncthreads();                 // all reads done before ring reuse
        if (c < 2 && tid == 0) issueChunk(c + 2, buf);
    }
    if (tid == 0) { mbar_inval(mb0); mbar_inval(mb0 + 8); }

    // ---- cross-quarter reduction via smem (reuse ring region) ----
    float* red = (float*)smc;            // 3 buffers of 32x34 floats (13KB)
    if (kh > 0) {
        float* r = red + (kh - 1) * (32 * 34);
#pragma unroll
        for (int mi = 0; mi < 2; mi++) {
            const int rl = mi * 16 + g;
#pragma unroll
            for (int nf = 0; nf < 2; nf++) {
                const int cc = wn * 16 + nf * 8 + 2 * t4;
                *(float2*)&r[rl * 34 + cc]       = make_float2(acc[mi][nf][0], acc[mi][nf][1]);
                *(float2*)&r[(rl + 8) * 34 + cc] = make_float2(acc[mi][nf][2], acc[mi][nf][3]);
            }
        }
    }
    __syncthreads();
    if (kh > 0) return;

#pragma unroll
    for (int b = 0; b < 3; b++) {
        const float* r = red + b * (32 * 34);
#pragma unroll
        for (int mi = 0; mi < 2; mi++) {
            const int rl = mi * 16 + g;
#pragma unroll
            for (int nf = 0; nf < 2; nf++) {
                const int cc = wn * 16 + nf * 8 + 2 * t4;
                float2 p0 = *(const float2*)&r[rl * 34 + cc];
                float2 p1 = *(const float2*)&r[(rl + 8) * 34 + cc];
                acc[mi][nf][0] += p0.x; acc[mi][nf][1] += p0.y;
                acc[mi][nf][2] += p1.x; acc[mi][nf][3] += p1.y;
            }
        }
    }

    // ---- epilogue (kh==0 warps: wn 0,1 cover all 32 cols) ----
#pragma unroll
    for (int mi = 0; mi < 2; mi++) {
        const int r0 = m0 + mi * 16 + g, r1 = r0 + 8;
#pragma unroll
        for (int nf = 0; nf < 2; nf++) {
            const int C = n0 + wn * 16 + nf * 8 + 2 * t4;
            if (MODE == 0) {
                float2 cb = *(const float2*)&cbar[C];
                float2 va = *(const float2*)&v2[r0 * DIMN + C];
                float2 vb = *(const float2*)&v2[r1 * DIMN + C];
                float c0 = va.x * acc[mi][nf][0] - cb.x;
                float c1 = va.y * acc[mi][nf][1] - cb.y;
                float c2 = vb.x * acc[mi][nf][2] - cb.x;
                float c3 = vb.y * acc[mi][nf][3] - cb.y;
                float u0 = __shfl_down_sync(0xffffffffu, c0, 2);
                float u1 = __shfl_down_sync(0xffffffffu, c1, 2);
                float u2 = __shfl_down_sync(0xffffffffu, c2, 2);
                float u3 = __shfl_down_sync(0xffffffffu, c3, 2);
                if (t4 < 2) {
                    const int p = mi * 8 + g;
                    const int ks_g = (n0 + wn * 16 + nf * 8) >> 3;
                    size_t base = (size_t)rb * A4_CNT + ks_g * 64 + p * 4;
                    g_tp4[base + 2 * t4] =
                        make_uint4(f2tf32(c0), f2tf32(u0), f2tf32(c2), f2tf32(u2));
                    g_tp4[base + 2 * t4 + 1] =
                        make_uint4(f2tf32(c1), f2tf32(u1), f2tf32(c3), f2tf32(u3));
                }
            } else {
                float* Out = (float*)OutV;
                float2 lb = *(const float2*)&linb[C];
                *(float2*)&Out[r0 * DIMN + C] =
                    make_float2(acc[mi][nf][0] + lb.x, acc[mi][nf][1] + lb.y);
                *(float2*)&Out[r1 * DIMN + C] =
                    make_float2(acc[mi][nf][2] + lb.x, acc[mi][nf][3] + lb.y);
            }
        }
    }
}

// ---------------------------------------------------------------------------
// Launch. Inputs: v1, v2, block_W, block_b, row_weights, lin_W, lin_b
// ---------------------------------------------------------------------------
extern "C" void kernel_launch(void* const* d_in, const int* in_sizes, int n_in,
                              void* d_out, int out_size) {
    const float* v1   = (const float*)d_in[0];
    const float* v2   = (const float*)d_in[1];
    const float* bW   = (const float*)d_in[2];
    const float* bB   = (const float*)d_in[3];
    const float* rw   = (const float*)d_in[4];
    const float* linW = (const float*)d_in[5];
    const float* linb = (const float*)d_in[6];

    const int nblocks = in_sizes[2] / (DIMN * DIMN);
    const int batch   = in_sizes[0] / DIMN;

    uint4 *gv1p4, *gtp4; uint2 *glwp, *gPtp; float* gcb;
    cudaGetSymbolAddress((void**)&gv1p4, g_v1p4);
    cudaGetSymbolAddress((void**)&gtp4,  g_tp4);
    cudaGetSymbolAddress((void**)&glwp,  g_lwp);
    cudaGetSymbolAddress((void**)&gPtp,  g_Ptp);
    cudaGetSymbolAddress((void**)&gcb,   g_cbar);

    cudaFuncSetAttribute(mma_gemm<0>, cudaFuncAttributeMaxDynamicSharedMemorySize, SMEM_GEMM);
    cudaFuncSetAttribute(mma_gemm<1>, cudaFuncAttributeMaxDynamicSharedMemorySize, SMEM_GEMM);

    cvt_pack_kernel<<<672, 256>>>(v1, linW);
    prep_kernel<<<dim3(12, 12), 256>>>(bW, bB, rw, nblocks);
    dim3 grid(DIMN / 32, batch / 32);   // (12, 32) = 384 CTAs
    mma_gemm<0><<<grid, 256, SMEM_GEMM>>>(gv1p4, gPtp, v2, gcb, nullptr, nullptr);
    mma_gemm<1><<<grid, 256, SMEM_GEMM>>>(gtp4, glwp, nullptr, nullptr, linb, d_out);
}